// round 16
// baseline (speedup 1.0000x reference)
#include <cuda_runtime.h>
#include <cuda_fp16.h>
#include <cstdint>

#define NN   10000
#define FIN  512
#define ED   256
#define H0D  512
#define H1D  256
#define NE   160000
#define TT   (NE + NN)

#define KACC  1e-5f
#define TINY  5e-4f

// ------------------------- device scratch (no allocs allowed) ---------------
__device__ float g_A[NN * H0D];
__device__ float g_B[NN * H0D];
__device__ __half g_W1h[H1D * H0D];
__device__ __half g_W1l[H1D * H0D];
__device__ __half g_Weh[ED * FIN];
__device__ __half g_Wel[ED * FIN];
__device__ __half g_W0h[H0D * H0D];
__device__ __half g_W0l[H0D * H0D];
__device__ float g_C;
__device__ float g_C2;
__device__ float g_lk[TT];
__device__ float g_elk[TT];
__device__ unsigned int g_segscr[NN];
__device__ unsigned long long g_seg2[NN];
__device__ int g_owner[NN];
__device__ int g_ncand;
__device__ int g_cand[TT];
__device__ int g_slot[TT];
__device__ float2 g_la[TT];
__device__ int g_nupd;
__device__ int g_upd[NN];

__device__ __forceinline__ unsigned int fenc(float f) {
    unsigned int u = __float_as_uint(f);
    return (u & 0x80000000u) ? ~u : (u | 0x80000000u);
}
__device__ __forceinline__ uint32_t smem_u32(const void* p) {
    uint32_t a;
    asm("{ .reg .u64 t; cvta.to.shared.u64 t, %1; cvt.u32.u64 %0, t; }"
        : "=r"(a) : "l"(p));
    return a;
}
__device__ __forceinline__ void ldsm4(uint32_t& r0, uint32_t& r1,
                                      uint32_t& r2, uint32_t& r3, uint32_t a) {
    asm volatile("ldmatrix.sync.aligned.m8n8.x4.shared.b16 {%0,%1,%2,%3}, [%4];"
                 : "=r"(r0), "=r"(r1), "=r"(r2), "=r"(r3) : "r"(a));
}
__device__ __forceinline__ void mma16816(float* c, const uint32_t* a,
                                         uint32_t b0, uint32_t b1) {
    asm volatile("mma.sync.aligned.m16n8k16.row.col.f32.f16.f16.f32 "
        "{%0,%1,%2,%3}, {%4,%5,%6,%7}, {%8,%9}, {%0,%1,%2,%3};"
        : "+f"(c[0]), "+f"(c[1]), "+f"(c[2]), "+f"(c[3])
        : "r"(a[0]), "r"(a[1]), "r"(a[2]), "r"(a[3]), "r"(b0), "r"(b1));
}
__device__ __forceinline__ void cp16ca(uint32_t s, const void* g) {
    asm volatile("cp.async.ca.shared.global [%0], [%1], 16;" :: "r"(s), "l"(g));
}
#define CP_COMMIT() asm volatile("cp.async.commit_group;" ::: "memory")
#define CP_WAIT0()  asm volatile("cp.async.wait_group 0;" ::: "memory")

// pack two halves (hi parts and lo parts) of two floats into packed words
__device__ __forceinline__ void split_pack(float x0, float x1,
                                           uint32_t& hw, uint32_t& lw) {
    __half h0 = __float2half_rn(x0), h1 = __float2half_rn(x1);
    __half l0 = __float2half_rn(x0 - __half2float(h0));
    __half l1 = __float2half_rn(x1 - __half2float(h1));
    hw = (uint32_t)__half_as_ushort(h0) | ((uint32_t)__half_as_ushort(h1) << 16);
    lw = (uint32_t)__half_as_ushort(l0) | ((uint32_t)__half_as_ushort(l1) << 16);
}

// ------------------------- merged prep: init + splits + C, C2 ---------------
__global__ void k_prep(const float* __restrict__ W1,
                       const float* __restrict__ We,
                       const float* __restrict__ W0,
                       const float* __restrict__ Wlk) {
    __shared__ float red[256];
    __shared__ float red2[256];
    const int b = blockIdx.x;
    if (b == 0) {
        int j = threadIdx.x;
        float s = 0.f, s2 = 0.f;
        for (int k = 0; k < H0D; k++) {
            float w = W1[(size_t)k * H1D + j];
            float wl = w - __half2float(__float2half_rn(w));
            s  = fmaf(w,  w,  s);
            s2 = fmaf(wl, wl, s2);
        }
        float awl = fabsf(Wlk[j]);
        red[j]  = sqrtf(s)  * awl;
        red2[j] = sqrtf(s2) * awl;
        __syncthreads();
        for (int o = 128; o; o >>= 1) {
            if (j < o) { red[j] += red[j + o]; red2[j] += red2[j + o]; }
            __syncthreads();
        }
        if (j == 0) { g_C = red[0]; g_C2 = red2[0]; }
        return;
    }
    int idx = (b - 1) * 256 + threadIdx.x;
    if (idx < NN) { g_segscr[idx] = 0u; g_seg2[idx] = 0ull; g_owner[idx] = -1; }
    if (idx == 0) { g_ncand = 0; g_nupd = 0; }
    if (idx < H1D * H0D) {
        int n = idx >> 9, k = idx & 511;
        float w = W1[(size_t)k * H1D + n];
        __half h = __float2half_rn(w);
        g_W1h[idx] = h;
        g_W1l[idx] = __float2half_rn(w - __half2float(h));
    }
    if (idx < ED * FIN) {
        int n = idx >> 9, k = idx & 511;
        float w = We[(size_t)k * ED + n];
        __half h = __float2half_rn(w);
        g_Weh[idx] = h;
        g_Wel[idx] = __float2half_rn(w - __half2float(h));
    }
    if (idx < H0D * H0D) {
        int n = idx >> 9, k = idx & 511;
        float w = W0[(size_t)k * H0D + n];
        __half h = __float2half_rn(w);
        g_W0h[idx] = h;
        g_W0l[idx] = __float2half_rn(w - __half2float(h));
    }
}

// ------------------------- HMMA tile constants ------------------------------
#define ASTR 40
#define OFF_AH 0
#define OFF_AL 2560
#define OFF_BH 5120
#define OFF_BL 15360
#define BUF_HALF 25600
#define HMMA_SMEM (2 * BUF_HALF * 2)
#define SBUF_HALF 15360
#define SCREEN_SMEM (2 * SBUF_HALF * 2)

// 3-term compute: warp tile 32m x 64n.
__device__ __forceinline__ void compute_phase3(
    uint32_t base, float (*acc)[4],
    uint32_t aRowB, uint32_t aCol, uint32_t bRow0, uint32_t bCol)
{
    #pragma unroll
    for (int ks = 0; ks < 2; ks++) {
        const uint32_t kofs = ks * 16;
        uint32_t ah[2][4], al[2][4];
        #pragma unroll
        for (int mt = 0; mt < 2; mt++) {
            ldsm4(ah[mt][0], ah[mt][1], ah[mt][2], ah[mt][3],
                  base + (OFF_AH + (aRowB + mt * 16) * ASTR + aCol + kofs) * 2);
            ldsm4(al[mt][0], al[mt][1], al[mt][2], al[mt][3],
                  base + (OFF_AL + (aRowB + mt * 16) * ASTR + aCol + kofs) * 2);
        }
        #pragma unroll
        for (int np = 0; np < 2; np++) {
            const uint32_t be_ = bRow0 + np * 32;
            const uint32_t bo_ = be_ + 16;
            uint32_t eh[4], el[4], oh[4], ol[4];
            ldsm4(eh[0], eh[1], eh[2], eh[3],
                  base + (OFF_BH + be_ * ASTR + bCol + kofs) * 2);
            ldsm4(el[0], el[1], el[2], el[3],
                  base + (OFF_BL + be_ * ASTR + bCol + kofs) * 2);
            ldsm4(oh[0], oh[1], oh[2], oh[3],
                  base + (OFF_BH + bo_ * ASTR + bCol + kofs) * 2);
            ldsm4(ol[0], ol[1], ol[2], ol[3],
                  base + (OFF_BL + bo_ * ASTR + bCol + kofs) * 2);
            #pragma unroll
            for (int mt = 0; mt < 2; mt++) {
                float* c0 = acc[mt * 8 + np * 4 + 0];
                float* c1 = acc[mt * 8 + np * 4 + 1];
                float* c2 = acc[mt * 8 + np * 4 + 2];
                float* c3 = acc[mt * 8 + np * 4 + 3];
                mma16816(c0, ah[mt], eh[0], eh[1]);
                mma16816(c1, ah[mt], eh[2], eh[3]);
                mma16816(c2, ah[mt], oh[0], oh[1]);
                mma16816(c3, ah[mt], oh[2], oh[3]);
                mma16816(c0, al[mt], eh[0], eh[1]);
                mma16816(c1, al[mt], eh[2], eh[3]);
                mma16816(c2, al[mt], oh[0], oh[1]);
                mma16816(c3, al[mt], oh[2], oh[3]);
                mma16816(c0, ah[mt], el[0], el[1]);
                mma16816(c1, ah[mt], el[2], el[3]);
                mma16816(c2, ah[mt], ol[0], ol[1]);
                mma16816(c3, ah[mt], ol[2], ol[3]);
            }
        }
    }
}

// 2-term compute (screen): (Ah+Al)*Bh.
__device__ __forceinline__ void compute_phase2(
    uint32_t base, float (*acc)[4],
    uint32_t aRowB, uint32_t aCol, uint32_t bRow0, uint32_t bCol)
{
    #pragma unroll
    for (int ks = 0; ks < 2; ks++) {
        const uint32_t kofs = ks * 16;
        uint32_t ah[2][4], al[2][4];
        #pragma unroll
        for (int mt = 0; mt < 2; mt++) {
            ldsm4(ah[mt][0], ah[mt][1], ah[mt][2], ah[mt][3],
                  base + (OFF_AH + (aRowB + mt * 16) * ASTR + aCol + kofs) * 2);
            ldsm4(al[mt][0], al[mt][1], al[mt][2], al[mt][3],
                  base + (OFF_AL + (aRowB + mt * 16) * ASTR + aCol + kofs) * 2);
        }
        #pragma unroll
        for (int np = 0; np < 2; np++) {
            const uint32_t be_ = bRow0 + np * 32;
            const uint32_t bo_ = be_ + 16;
            uint32_t eh[4], oh[4];
            ldsm4(eh[0], eh[1], eh[2], eh[3],
                  base + (OFF_BH + be_ * ASTR + bCol + kofs) * 2);
            ldsm4(oh[0], oh[1], oh[2], oh[3],
                  base + (OFF_BH + bo_ * ASTR + bCol + kofs) * 2);
            #pragma unroll
            for (int mt = 0; mt < 2; mt++) {
                float* c0 = acc[mt * 8 + np * 4 + 0];
                float* c1 = acc[mt * 8 + np * 4 + 1];
                float* c2 = acc[mt * 8 + np * 4 + 2];
                float* c3 = acc[mt * 8 + np * 4 + 3];
                mma16816(c0, ah[mt], eh[0], eh[1]);
                mma16816(c1, ah[mt], eh[2], eh[3]);
                mma16816(c2, ah[mt], oh[0], oh[1]);
                mma16816(c3, ah[mt], oh[2], oh[3]);
                mma16816(c0, al[mt], eh[0], eh[1]);
                mma16816(c1, al[mt], eh[2], eh[3]);
                mma16816(c2, al[mt], oh[0], oh[1]);
                mma16816(c3, al[mt], oh[2], oh[3]);
            }
        }
    }
}

// ------------------------- pipelined split-HMMA GEMM (3-term) ---------------
__global__ void __launch_bounds__(256, 2)
k_hgemm(const float* __restrict__ A, int lda, int M, int nkb,
        int bsel, int zfuse, const float* __restrict__ bias,
        float* __restrict__ Cp, int csel0, int ldc, int do_relu)
{
    extern __shared__ __align__(16) __half smh[];
    __shared__ float s_bias[256];

    const int z = zfuse ? blockIdx.z : 0;
    const int csel = csel0 + z;
    const int koff = z * 256;
    float* C = (csel == 1) ? g_A : (csel == 2) ? g_B : Cp;
    const __half* BTh = bsel ? g_W0h : g_Weh;
    const __half* BTl = bsel ? g_W0l : g_Wel;
    const float* bias_eff = (csel == 2) ? nullptr : bias;

    const int tid = threadIdx.x, wid = tid >> 5, lane = tid & 31;
    const int wm = wid & 1, wn = wid >> 1;
    const int row0 = blockIdx.x * 64;
    const int n0 = blockIdx.y * 256;

    s_bias[tid] = bias_eff ? bias_eff[n0 + tid] : 0.f;

    const int ar = tid >> 2, kq = (tid & 3) * 8;
    const int grow = row0 + ar;
    const float4* pA = (const float4*)(A + (size_t)(grow < M ? grow : 0) * lda);

    const uint32_t sb = smem_u32(smh);
    const uint32_t aRowB = wm * 32 + (lane & 15);
    const uint32_t aCol = (lane < 16) ? 0 : 8;
    const uint32_t bRow0 = wn * 64 + (lane & 7) + ((lane >= 16) ? 8 : 0);
    const uint32_t bCol = (lane & 8) ? 8 : 0;

    float acc[16][4];
    #pragma unroll
    for (int i = 0; i < 16; i++)
        #pragma unroll
        for (int j = 0; j < 4; j++) acc[i][j] = 0.f;

    auto ldgA = [&](int kb, float4& r0, float4& r1) {
        int f4 = kb * 8 + (tid & 3) * 2;
        if (grow < M) { r0 = __ldcg(pA + f4); r1 = __ldcg(pA + f4 + 1); }
        else { r0 = make_float4(0.f,0.f,0.f,0.f); r1 = r0; }
    };
    auto stsA = [&](int buf, float4 a0, float4 a1) {
        float v[8] = {a0.x, a0.y, a0.z, a0.w, a1.x, a1.y, a1.z, a1.w};
        uint32_t hw[4], lw[4];
        #pragma unroll
        for (int e = 0; e < 4; e++)
            split_pack(v[2 * e], v[2 * e + 1], hw[e], lw[e]);
        *(uint4*)(smh + buf * BUF_HALF + OFF_AH + ar * ASTR + kq) =
            make_uint4(hw[0], hw[1], hw[2], hw[3]);
        *(uint4*)(smh + buf * BUF_HALF + OFF_AL + ar * ASTR + kq) =
            make_uint4(lw[0], lw[1], lw[2], lw[3]);
    };
    auto stageB = [&](int kb, int buf) {
        const __half* srcH = BTh + (size_t)(n0 + tid) * 512 + koff + kb * 32;
        const __half* srcL = BTl + (size_t)(n0 + tid) * 512 + koff + kb * 32;
        uint32_t dH = sb + (buf * BUF_HALF + OFF_BH + tid * ASTR) * 2;
        uint32_t dL = sb + (buf * BUF_HALF + OFF_BL + tid * ASTR) * 2;
        #pragma unroll
        for (int q = 0; q < 4; q++) {
            cp16ca(dH + q * 16, srcH + q * 8);
            cp16ca(dL + q * 16, srcL + q * 8);
        }
    };

    float4 ra0, ra1;
    ldgA(0, ra0, ra1);
    stsA(0, ra0, ra1);
    stageB(0, 0); CP_COMMIT();
    if (nkb > 1) ldgA(1, ra0, ra1);
    CP_WAIT0();
    __syncthreads();

    for (int kb = 0; kb < nkb; kb++) {
        const int cur = kb & 1;
        if (kb + 1 < nkb) {
            stsA(cur ^ 1, ra0, ra1);
            stageB(kb + 1, cur ^ 1); CP_COMMIT();
            if (kb + 2 < nkb) ldgA(kb + 2, ra0, ra1);
        }
        compute_phase3(sb + cur * BUF_HALF * 2, acc, aRowB, aCol, bRow0, bCol);
        if (kb + 1 < nkb) CP_WAIT0();
        __syncthreads();
    }

    const int g = lane >> 2, tg = lane & 3;
    #pragma unroll
    for (int mt = 0; mt < 2; mt++) {
        const int r0 = row0 + wm * 32 + mt * 16 + g;
        const int r1 = r0 + 8;
        #pragma unroll
        for (int ntc = 0; ntc < 8; ntc++) {
            int c = wn * 64 + ntc * 8 + tg * 2;
            float* a = acc[mt * 8 + ntc];
            float b0v = s_bias[c], b1v = s_bias[c + 1];
            float v00 = a[0] + b0v, v01 = a[1] + b1v;
            float v10 = a[2] + b0v, v11 = a[3] + b1v;
            if (do_relu) {
                v00 = fmaxf(v00, 0.f); v01 = fmaxf(v01, 0.f);
                v10 = fmaxf(v10, 0.f); v11 = fmaxf(v11, 0.f);
            }
            if (r0 < M) *(float2*)&C[(size_t)r0 * ldc + n0 + c] = make_float2(v00, v01);
            if (r1 < M) *(float2*)&C[(size_t)r1 * ldc + n0 + c] = make_float2(v10, v11);
        }
    }
}

// ------------------------- pipelined 2-term HMMA screening ------------------
__global__ void __launch_bounds__(256, 2)
k_screen(const float* __restrict__ b1, const float* __restrict__ Wlk,
         const float* __restrict__ blk,
         const int* __restrict__ esrc, const int* __restrict__ edst)
{
    extern __shared__ __align__(16) __half smh[];
    __shared__ float s_n2[64];
    __shared__ float s_lk[4][64];
    __shared__ int s_src[64], s_dst[64];
    __shared__ float s_b1[256], s_wlk[256];

    const int tid = threadIdx.x, wid = tid >> 5, lane = tid & 31;
    const int wm = wid & 1, wn = wid >> 1;
    const int t0 = blockIdx.x * 64;

    if (tid < 64) {
        int t = t0 + tid;
        int s = -1, d = -1;
        if (t < TT) {
            if (t < NE) { s = esrc[t]; d = edst[t]; }
            else        { s = t - NE; }
        }
        s_src[tid] = s; s_dst[tid] = d;
        s_n2[tid] = 0.f;
    }
    s_b1[tid]  = b1[tid];
    s_wlk[tid] = Wlk[tid];
    __syncthreads();

    const int ar = tid >> 2, kq = (tid & 3) * 8;
    const int ss = s_src[ar], dd = s_dst[ar];
    const float4* pA = (const float4*)(g_A + (size_t)(ss < 0 ? 0 : ss) * H0D);
    const float4* pB = (const float4*)(g_B + (size_t)(dd < 0 ? 0 : dd) * H0D);

    const uint32_t sb = smem_u32(smh);
    const uint32_t aRowB = wm * 32 + (lane & 15);
    const uint32_t aCol = (lane < 16) ? 0 : 8;
    const uint32_t bRow0 = wn * 64 + (lane & 7) + ((lane >= 16) ? 8 : 0);
    const uint32_t bCol = (lane & 8) ? 8 : 0;

    float acc[16][4];
    #pragma unroll
    for (int i = 0; i < 16; i++)
        #pragma unroll
        for (int j = 0; j < 4; j++) acc[i][j] = 0.f;

    float n2acc = 0.f;

    auto ldgA = [&](int kb, float4* r) {
        int f4 = kb * 8 + (tid & 3) * 2;
        if (ss >= 0) {
            r[0] = __ldcg(pA + f4); r[1] = __ldcg(pA + f4 + 1);
            if (dd >= 0) { r[2] = __ldcg(pB + f4); r[3] = __ldcg(pB + f4 + 1); }
            else { r[2] = make_float4(0.f,0.f,0.f,0.f); r[3] = r[2]; }
        } else {
            r[0] = make_float4(0.f,0.f,0.f,0.f);
            r[1] = r[0]; r[2] = r[0]; r[3] = r[0];
        }
    };
    auto stsA = [&](int buf, const float4* r) {
        float v[8] = {r[0].x + r[2].x, r[0].y + r[2].y,
                      r[0].z + r[2].z, r[0].w + r[2].w,
                      r[1].x + r[3].x, r[1].y + r[3].y,
                      r[1].z + r[3].z, r[1].w + r[3].w};
        uint32_t hw[4], lw[4];
        #pragma unroll
        for (int e = 0; e < 4; e++) {
            float x0 = fmaxf(v[2 * e],     0.f);
            float x1 = fmaxf(v[2 * e + 1], 0.f);
            split_pack(x0, x1, hw[e], lw[e]);
            n2acc = fmaf(x0, x0, n2acc);
            n2acc = fmaf(x1, x1, n2acc);
        }
        *(uint4*)(smh + buf * SBUF_HALF + OFF_AH + ar * ASTR + kq) =
            make_uint4(hw[0], hw[1], hw[2], hw[3]);
        *(uint4*)(smh + buf * SBUF_HALF + OFF_AL + ar * ASTR + kq) =
            make_uint4(lw[0], lw[1], lw[2], lw[3]);
    };
    auto stageB = [&](int kb, int buf) {
        const __half* srcH = g_W1h + (size_t)tid * H0D + kb * 32;
        uint32_t dH = sb + (buf * SBUF_HALF + OFF_BH + tid * ASTR) * 2;
        #pragma unroll
        for (int q = 0; q < 4; q++)
            cp16ca(dH + q * 16, srcH + q * 8);
    };

    float4 ra[4];
    ldgA(0, ra);
    stsA(0, ra);
    stageB(0, 0); CP_COMMIT();
    ldgA(1, ra);
    CP_WAIT0();
    __syncthreads();

    const int nkb = 16;
    for (int kb = 0; kb < nkb; kb++) {
        const int cur = kb & 1;
        if (kb + 1 < nkb) {
            stsA(cur ^ 1, ra);
            stageB(kb + 1, cur ^ 1); CP_COMMIT();
            if (kb + 2 < nkb) ldgA(kb + 2, ra);
        }
        compute_phase2(sb + cur * SBUF_HALF * 2, acc, aRowB, aCol, bRow0, bCol);
        if (kb + 1 < nkb) CP_WAIT0();
        __syncthreads();
    }

    if (ss >= 0) atomicAdd(&s_n2[ar], n2acc);

    const int g = lane >> 2, tg = lane & 3;
    float sum[2][2] = {{0.f, 0.f}, {0.f, 0.f}};
    #pragma unroll
    for (int mt = 0; mt < 2; mt++) {
        #pragma unroll
        for (int ntc = 0; ntc < 8; ntc++) {
            int c = wn * 64 + ntc * 8 + tg * 2;
            float* a = acc[mt * 8 + ntc];
            float b10 = s_b1[c],     w0 = s_wlk[c];
            float b11 = s_b1[c + 1], w1 = s_wlk[c + 1];
            sum[mt][0] += fmaxf(a[0] + b10, 0.f) * w0 +
                          fmaxf(a[1] + b11, 0.f) * w1;
            sum[mt][1] += fmaxf(a[2] + b10, 0.f) * w0 +
                          fmaxf(a[3] + b11, 0.f) * w1;
        }
    }
    #pragma unroll
    for (int mt = 0; mt < 2; mt++) {
        sum[mt][0] += __shfl_xor_sync(0xffffffffu, sum[mt][0], 1);
        sum[mt][0] += __shfl_xor_sync(0xffffffffu, sum[mt][0], 2);
        sum[mt][1] += __shfl_xor_sync(0xffffffffu, sum[mt][1], 1);
        sum[mt][1] += __shfl_xor_sync(0xffffffffu, sum[mt][1], 2);
    }
    __syncthreads();
    if (tg == 0) {
        #pragma unroll
        for (int mt = 0; mt < 2; mt++) {
            s_lk[wn][wm * 32 + mt * 16 + g]     = sum[mt][0];
            s_lk[wn][wm * 32 + mt * 16 + g + 8] = sum[mt][1];
        }
    }
    __syncthreads();

    if (tid < 64) {
        int t = t0 + tid;
        if (t < TT) {
            float lk = s_lk[0][tid] + s_lk[1][tid] + s_lk[2][tid] +
                       s_lk[3][tid] + blk[0];
            float err = (1.02f * g_C2 + KACC * g_C) * sqrtf(s_n2[tid]) + TINY;
            g_lk[t] = lk;
            g_elk[t] = err;
            atomicMax(&g_segscr[s_src[tid]], fenc(lk - err));
        }
    }
}

// ------------------------- candidate compaction -----------------------------
__global__ void k_compact(const int* __restrict__ esrc) {
    int t = blockIdx.x * blockDim.x + threadIdx.x;
    if (t >= TT) return;
    int s = (t < NE) ? esrc[t] : (t - NE);
    if (fenc(g_lk[t] + g_elk[t]) >= g_segscr[s]) {
        int slot = atomicAdd(&g_ncand, 1);
        g_cand[slot] = t;
        g_slot[t] = slot;
    }
}

// ------------- exact fp32 rescore + fused action head (occ unbounded) -------
__global__ __launch_bounds__(256) void k_rescore(
    const float* __restrict__ W1, const float* __restrict__ b1,
    const float* __restrict__ Wlk, const float* __restrict__ blk,
    const float* __restrict__ Wa,
    const int* __restrict__ esrc, const int* __restrict__ edst)
{
    const int c0 = blockIdx.x * 64;
    const int nc = g_ncand;
    if (c0 >= nc) return;

    __shared__ float Zs[32][68];
    __shared__ float Bs[32 * 256];
    __shared__ int s_src[64], s_dst[64], s_t[64];

    const int tid = threadIdx.x;
    const int cg = tid & 31, eg = tid >> 5;

    if (tid < 64) {
        int c = c0 + tid;
        int s = -1, d = -1, t = -1;
        if (c < nc) {
            t = g_cand[c];
            if (t < NE) { s = esrc[t]; d = edst[t]; }
            else        { s = t - NE; }
        }
        s_src[tid] = s; s_dst[tid] = d; s_t[tid] = t;
    }
    __syncthreads();

    float acc[8][8];
    #pragma unroll
    for (int i = 0; i < 8; i++)
        #pragma unroll
        for (int j = 0; j < 8; j++) acc[i][j] = 0.f;

    for (int k0 = 0; k0 < H0D; k0 += 32) {
        #pragma unroll
        for (int l = 0; l < 8; l++) {
            int idx = tid + l * 256;
            int e = idx >> 5, kk = idx & 31;
            int s = s_src[e];
            float v = 0.f;
            if (s >= 0) {
                v = g_A[(size_t)s * H0D + k0 + kk];
                int d = s_dst[e];
                if (d >= 0) v += g_B[(size_t)d * H0D + k0 + kk];
                v = fmaxf(v, 0.f);
            }
            Zs[kk][e] = v;
        }
        #pragma unroll
        for (int l = 0; l < 8; l++) {
            int idx4 = tid + l * 256;
            int kk = idx4 >> 6, c = (idx4 << 2) & 255;
            *(float4*)&Bs[kk * 256 + c] =
                *(const float4*)&W1[(size_t)(k0 + kk) * H1D + c];
        }
        __syncthreads();
        #pragma unroll
        for (int kk = 0; kk < 32; kk++) {
            float a[8], b[8];
            *(float4*)(a)     = *(const float4*)&Zs[kk][eg * 8];
            *(float4*)(a + 4) = *(const float4*)&Zs[kk][eg * 8 + 4];
            *(float4*)(b)     = *(const float4*)&Bs[kk * 256 + cg * 8];
            *(float4*)(b + 4) = *(const float4*)&Bs[kk * 256 + cg * 8 + 4];
            #pragma unroll
            for (int i = 0; i < 8; i++)
                #pragma unroll
                for (int j = 0; j < 8; j++)
                    acc[i][j] = fmaf(a[i], b[j], acc[i][j]);
        }
        __syncthreads();
    }

    float bb[8], wl[8], wa0[8], wa1[8];
    #pragma unroll
    for (int j = 0; j < 8; j++) {
        int c = cg * 8 + j;
        bb[j]  = b1[c];
        wl[j]  = Wlk[c];
        wa0[j] = Wa[c * 2 + 0];
        wa1[j] = Wa[c * 2 + 1];
    }

    #pragma unroll
    for (int i = 0; i < 8; i++) {
        int e = eg * 8 + i;
        float p = 0.f, q0 = 0.f, q1 = 0.f;
        #pragma unroll
        for (int j = 0; j < 8; j++) {
            float h = fmaxf(acc[i][j] + bb[j], 0.f);
            p  = fmaf(h, wl[j],  p);
            q0 = fmaf(h, wa0[j], q0);
            q1 = fmaf(h, wa1[j], q1);
        }
        #pragma unroll
        for (int off = 16; off; off >>= 1) {
            p  += __shfl_xor_sync(0xffffffffu, p,  off);
            q0 += __shfl_xor_sync(0xffffffffu, q0, off);
            q1 += __shfl_xor_sync(0xffffffffu, q1, off);
        }
        if (cg == 0) {
            int t = s_t[e];
            if (t >= 0) {
                float lk = p + blk[0];
                unsigned long long key =
                    ((unsigned long long)fenc(lk) << 32) | (unsigned int)t;
                atomicMax(&g_seg2[s_src[e]], key);
                g_la[c0 + e] = make_float2(q0, q1);
            }
        }
    }
}

// ------------------------- winner decode ------------------------------------
__global__ void k_final(const float* __restrict__ ba,
                        const int* __restrict__ edst)
{
    int i = blockIdx.x * blockDim.x + threadIdx.x;
    if (i >= NN) return;
    unsigned long long key = g_seg2[i];
    int win = (int)(unsigned int)(key & 0xffffffffull);
    int chosen = (win < NE) ? edst[win] : -1;
    if (chosen < 0) return;
    float2 la = g_la[g_slot[win]];
    float l0 = la.x + ba[0], l1 = la.y + ba[1];
    if (l1 > l0)
        atomicMax(&g_owner[chosen], i);
}

// ------------------------- compact update targets ---------------------------
__global__ void k_compact2() {
    int t = blockIdx.x * blockDim.x + threadIdx.x;
    if (t < NN && g_owner[t] >= 0) {
        int s = atomicAdd(&g_nupd, 1);
        g_upd[s] = t;
    }
}

// ------------------------- split-HMMA update of chosen rows -----------------
__global__ void __launch_bounds__(256, 2)
k_updval(const float* __restrict__ feature, const float* __restrict__ be,
         float* __restrict__ out)
{
    const int c0 = blockIdx.x * 64;
    const int nu = g_nupd;
    if (c0 >= nu) return;

    extern __shared__ __align__(16) __half smh[];
    __shared__ int s_t[64], s_i[64];
    __shared__ float s_be[256];

    const int tid = threadIdx.x, wid = tid >> 5, lane = tid & 31;
    const int wm = wid & 1, wn = wid >> 1;

    if (tid < 64) {
        int c = c0 + tid;
        int t = (c < nu) ? g_upd[c] : -1;
        s_t[tid] = t;
        s_i[tid] = (t >= 0) ? g_owner[t] : 0;
    }
    s_be[tid] = be[tid];
    __syncthreads();

    const int ar = tid >> 2, kq = (tid & 3) * 8;
    const int tt = s_t[ar], ii = s_i[ar];
    const float4* pA = (const float4*)(feature + (size_t)(tt < 0 ? 0 : tt) * FIN);
    const float4* pB = (const float4*)(feature + (size_t)ii * FIN);

    const uint32_t sb = smem_u32(smh);
    const uint32_t aRowB = wm * 32 + (lane & 15);
    const uint32_t aCol = (lane < 16) ? 0 : 8;
    const uint32_t bRow0 = wn * 64 + (lane & 7) + ((lane >= 16) ? 8 : 0);
    const uint32_t bCol = (lane & 8) ? 8 : 0;

    float acc[16][4];
    #pragma unroll
    for (int i = 0; i < 16; i++)
        #pragma unroll
        for (int j = 0; j < 4; j++) acc[i][j] = 0.f;

    auto ldgA = [&](int kb, float4* r) {
        int f4 = kb * 8 + (tid & 3) * 2;
        if (tt >= 0) {
            r[0] = __ldcg(pA + f4); r[1] = __ldcg(pA + f4 + 1);
            r[2] = __ldcg(pB + f4); r[3] = __ldcg(pB + f4 + 1);
        } else {
            r[0] = make_float4(0.f,0.f,0.f,0.f);
            r[1] = r[0]; r[2] = r[0]; r[3] = r[0];
        }
    };
    auto stsA = [&](int buf, const float4* r) {
        float v[8] = {0.5f * (r[0].x + r[2].x), 0.5f * (r[0].y + r[2].y),
                      0.5f * (r[0].z + r[2].z), 0.5f * (r[0].w + r[2].w),
                      0.5f * (r[1].x + r[3].x), 0.5f * (r[1].y + r[3].y),
                      0.5f * (r[1].z + r[3].z), 0.5f * (r[1].w + r[3].w)};
        uint32_t hw[4], lw[4];
        #pragma unroll
        for (int e = 0; e < 4; e++)
            split_pack(v[2 * e], v[2 * e + 1], hw[e], lw[e]);
        *(uint4*)(smh + buf * BUF_HALF + OFF_AH + ar * ASTR + kq) =
            make_uint4(hw[0], hw[1], hw[2], hw[3]);
        *(uint4*)(smh + buf * BUF_HALF + OFF_AL + ar * ASTR + kq) =
            make_uint4(lw[0], lw[1], lw[2], lw[3]);
    };
    auto stageB = [&](int kb, int buf) {
        const __half* srcH = g_Weh + (size_t)tid * FIN + kb * 32;
        const __half* srcL = g_Wel + (size_t)tid * FIN + kb * 32;
        uint32_t dH = sb + (buf * BUF_HALF + OFF_BH + tid * ASTR) * 2;
        uint32_t dL = sb + (buf * BUF_HALF + OFF_BL + tid * ASTR) * 2;
        #pragma unroll
        for (int q = 0; q < 4; q++) {
            cp16ca(dH + q * 16, srcH + q * 8);
            cp16ca(dL + q * 16, srcL + q * 8);
        }
    };

    float4 ra[4];
    ldgA(0, ra);
    stsA(0, ra);
    stageB(0, 0); CP_COMMIT();
    ldgA(1, ra);
    CP_WAIT0();
    __syncthreads();

    const int nkb = 16;
    for (int kb = 0; kb < nkb; kb++) {
        const int cur = kb & 1;
        if (kb + 1 < nkb) {
            stsA(cur ^ 1, ra);
            stageB(kb + 1, cur ^ 1); CP_COMMIT();
            if (kb + 2 < nkb) ldgA(kb + 2, ra);
        }
        compute_phase3(sb + cur * BUF_HALF * 2, acc, aRowB, aCol, bRow0, bCol);
        if (kb + 1 < nkb) CP_WAIT0();
        __syncthreads();
    }

    const int g = lane >> 2, tg = lane & 3;
    #pragma unroll
    for (int mt = 0; mt < 2; mt++) {
        const int e0 = wm * 32 + mt * 16 + g;
        const int e1 = e0 + 8;
        const int t0r = s_t[e0], t1r = s_t[e1];
        #pragma unroll
        for (int ntc = 0; ntc < 8; ntc++) {
            int c = wn * 64 + ntc * 8 + tg * 2;
            float* a = acc[mt * 8 + ntc];
            float b0v = s_be[c], b1v = s_be[c + 1];
            float v00 = fmaxf(a[0] + b0v, 0.f), v01 = fmaxf(a[1] + b1v, 0.f);
            float v10 = fmaxf(a[2] + b0v, 0.f), v11 = fmaxf(a[3] + b1v, 0.f);
            if (t0r >= 0) *(float2*)&out[(size_t)t0r * ED + c] = make_float2(v00, v01);
            if (t1r >= 0) *(float2*)&out[(size_t)t1r * ED + c] = make_float2(v10, v11);
        }
    }
}

// ---------------------------------------------------------------------------
extern "C" void kernel_launch(void* const* d_in, const int* in_sizes, int n_in,
                              void* d_out, int out_size) {
    const float* feature = (const float*)d_in[0];
    const float* We      = (const float*)d_in[1];
    const float* be      = (const float*)d_in[2];
    const float* W0      = (const float*)d_in[3];
    const float* b0      = (const float*)d_in[4];
    const float* W1      = (const float*)d_in[5];
    const float* b1      = (const float*)d_in[6];
    const float* Wlk     = (const float*)d_in[7];
    const float* blk     = (const float*)d_in[8];
    const float* Wa      = (const float*)d_in[9];
    const float* ba      = (const float*)d_in[10];
    const int*   esrc    = (const int*)d_in[11];
    const int*   edst    = (const int*)d_in[12];
    float* out = (float*)d_out;

    static int smem_set = 0;
    if (!smem_set) {
        cudaFuncSetAttribute(k_screen,
                             cudaFuncAttributeMaxDynamicSharedMemorySize,
                             SCREEN_SMEM);
        cudaFuncSetAttribute(k_hgemm,
                             cudaFuncAttributeMaxDynamicSharedMemorySize,
                             HMMA_SMEM);
        cudaFuncSetAttribute(k_updval,
                             cudaFuncAttributeMaxDynamicSharedMemorySize,
                             HMMA_SMEM);
        smem_set = 1;
    }

    k_prep<<<1 + (H0D * H0D + 255) / 256, 256>>>(W1, We, W0, Wlk);
    k_hgemm<<<dim3(157, 1, 1), 256, HMMA_SMEM>>>(
        feature, FIN, NN, 16, 0, 0, be, out, 0, ED, 1);
    k_hgemm<<<dim3(157, 2, 2), 256, HMMA_SMEM>>>(
        out, ED, NN, 8, 1, 1, b0, nullptr, 1, H0D, 0);
    // launch #4 (profiled): 2-term screening
    k_screen<<<(TT + 63) / 64, 256, SCREEN_SMEM>>>(b1, Wlk, blk, esrc, edst);

    k_compact<<<(TT + 255) / 256, 256>>>(esrc);
    k_rescore<<<(TT + 63) / 64, 256>>>(W1, b1, Wlk, blk, Wa, esrc, edst);
    k_final<<<(NN + 255) / 256, 256>>>(ba, edst);
    k_compact2<<<(NN + 255) / 256, 256>>>();
    k_updval<<<(NN + 63) / 64, 256, HMMA_SMEM>>>(feature, be, out);
}

// round 17
// speedup vs baseline: 1.0934x; 1.0934x over previous
#include <cuda_runtime.h>
#include <cuda_fp16.h>
#include <cstdint>

#define NN   10000
#define FIN  512
#define ED   256
#define H0D  512
#define H1D  256
#define NE   160000
#define TT   (NE + NN)

#define KACC  1e-5f       // fp32 accumulation slack (derived, 2x margin)
#define TINY  5e-4f       // epilogue noise floor

// ------------------------- device scratch (no allocs allowed) ---------------
__device__ float g_A[NN * H0D];
__device__ float g_B[NN * H0D];
__device__ __half g_W1h[H1D * H0D];
__device__ __half g_W1l[H1D * H0D];
__device__ __half g_Weh[ED * FIN];
__device__ __half g_Wel[ED * FIN];
__device__ __half g_W0h[H0D * H0D];
__device__ __half g_W0l[H0D * H0D];
__device__ float g_C;      // sum_j ||W1_:j|| * |Wlk_j|
__device__ float g_C2;     // sum_j ||W1l_:j|| * |Wlk_j| (exact dropped-term const)
__device__ float g_lk[TT];
__device__ float g_elk[TT];
__device__ unsigned int g_segscr[NN];
__device__ unsigned long long g_seg2[NN];
__device__ int g_owner[NN];
__device__ int g_ncand;
__device__ int g_cand[TT];
__device__ int g_slot[TT];
__device__ float g_h_cand[(size_t)TT * H1D];
__device__ int g_nupd;
__device__ int g_upd[NN];

__device__ __forceinline__ unsigned int fenc(float f) {
    unsigned int u = __float_as_uint(f);
    return (u & 0x80000000u) ? ~u : (u | 0x80000000u);
}
__device__ __forceinline__ uint32_t smem_u32(const void* p) {
    uint32_t a;
    asm("{ .reg .u64 t; cvta.to.shared.u64 t, %1; cvt.u32.u64 %0, t; }"
        : "=r"(a) : "l"(p));
    return a;
}
__device__ __forceinline__ void ldsm4(uint32_t& r0, uint32_t& r1,
                                      uint32_t& r2, uint32_t& r3, uint32_t a) {
    asm volatile("ldmatrix.sync.aligned.m8n8.x4.shared.b16 {%0,%1,%2,%3}, [%4];"
                 : "=r"(r0), "=r"(r1), "=r"(r2), "=r"(r3) : "r"(a));
}
__device__ __forceinline__ void mma16816(float* c, const uint32_t* a,
                                         uint32_t b0, uint32_t b1) {
    asm volatile("mma.sync.aligned.m16n8k16.row.col.f32.f16.f16.f32 "
        "{%0,%1,%2,%3}, {%4,%5,%6,%7}, {%8,%9}, {%0,%1,%2,%3};"
        : "+f"(c[0]), "+f"(c[1]), "+f"(c[2]), "+f"(c[3])
        : "r"(a[0]), "r"(a[1]), "r"(a[2]), "r"(a[3]), "r"(b0), "r"(b1));
}
// L2-only copy (default path, as in R14)
__device__ __forceinline__ void cp16(uint32_t s, const void* g) {
    asm volatile("cp.async.cg.shared.global [%0], [%1], 16;" :: "r"(s), "l"(g));
}
// L1-cached copy (screen weight staging only — isolated R15 win)
__device__ __forceinline__ void cp16ca(uint32_t s, const void* g) {
    asm volatile("cp.async.ca.shared.global [%0], [%1], 16;" :: "r"(s), "l"(g));
}
#define CP_COMMIT() asm volatile("cp.async.commit_group;" ::: "memory")
#define CP_WAIT0()  asm volatile("cp.async.wait_group 0;" ::: "memory")

// ------------------------- merged prep: init + splits + C, C2 ---------------
__global__ void k_prep(const float* __restrict__ W1,
                       const float* __restrict__ We,
                       const float* __restrict__ W0,
                       const float* __restrict__ Wlk) {
    __shared__ float red[256];
    __shared__ float red2[256];
    const int b = blockIdx.x;
    if (b == 0) {
        int j = threadIdx.x;
        float s = 0.f, s2 = 0.f;
        for (int k = 0; k < H0D; k++) {
            float w = W1[(size_t)k * H1D + j];
            float wl = w - __half2float(__float2half_rn(w));
            s  = fmaf(w,  w,  s);
            s2 = fmaf(wl, wl, s2);
        }
        float awl = fabsf(Wlk[j]);
        red[j]  = sqrtf(s)  * awl;
        red2[j] = sqrtf(s2) * awl;
        __syncthreads();
        for (int o = 128; o; o >>= 1) {
            if (j < o) { red[j] += red[j + o]; red2[j] += red2[j + o]; }
            __syncthreads();
        }
        if (j == 0) { g_C = red[0]; g_C2 = red2[0]; }
        return;
    }
    int idx = (b - 1) * 256 + threadIdx.x;
    if (idx < NN) { g_segscr[idx] = 0u; g_seg2[idx] = 0ull; g_owner[idx] = -1; }
    if (idx == 0) { g_ncand = 0; g_nupd = 0; }
    if (idx < H1D * H0D) {
        int n = idx >> 9, k = idx & 511;
        float w = W1[(size_t)k * H1D + n];
        __half h = __float2half_rn(w);
        g_W1h[idx] = h;
        g_W1l[idx] = __float2half_rn(w - __half2float(h));
    }
    if (idx < ED * FIN) {
        int n = idx >> 9, k = idx & 511;
        float w = We[(size_t)k * ED + n];
        __half h = __float2half_rn(w);
        g_Weh[idx] = h;
        g_Wel[idx] = __float2half_rn(w - __half2float(h));
    }
    if (idx < H0D * H0D) {
        int n = idx >> 9, k = idx & 511;
        float w = W0[(size_t)k * H0D + n];
        __half h = __float2half_rn(w);
        g_W0h[idx] = h;
        g_W0l[idx] = __float2half_rn(w - __half2float(h));
    }
}

// ------------------------- HMMA tile constants ------------------------------
#define ASTR 40
#define OFF_AH 0
#define OFF_AL 2560
#define OFF_BH 5120
#define OFF_BL 15360
#define BUF_HALF 25600
#define HMMA_SMEM (2 * BUF_HALF * 2)
#define SBUF_HALF 15360
#define SCREEN_SMEM (2 * SBUF_HALF * 2)

// 3-term compute (prep/updval): warp tile 32m x 64n.
__device__ __forceinline__ void compute_phase3(
    uint32_t base, float (*acc)[4],
    uint32_t aRowB, uint32_t aCol, uint32_t bRow0, uint32_t bCol)
{
    #pragma unroll
    for (int ks = 0; ks < 2; ks++) {
        const uint32_t kofs = ks * 16;
        uint32_t ah[2][4], al[2][4];
        #pragma unroll
        for (int mt = 0; mt < 2; mt++) {
            ldsm4(ah[mt][0], ah[mt][1], ah[mt][2], ah[mt][3],
                  base + (OFF_AH + (aRowB + mt * 16) * ASTR + aCol + kofs) * 2);
            ldsm4(al[mt][0], al[mt][1], al[mt][2], al[mt][3],
                  base + (OFF_AL + (aRowB + mt * 16) * ASTR + aCol + kofs) * 2);
        }
        #pragma unroll
        for (int np = 0; np < 2; np++) {
            const uint32_t be_ = bRow0 + np * 32;
            const uint32_t bo_ = be_ + 16;
            uint32_t eh[4], el[4], oh[4], ol[4];
            ldsm4(eh[0], eh[1], eh[2], eh[3],
                  base + (OFF_BH + be_ * ASTR + bCol + kofs) * 2);
            ldsm4(el[0], el[1], el[2], el[3],
                  base + (OFF_BL + be_ * ASTR + bCol + kofs) * 2);
            ldsm4(oh[0], oh[1], oh[2], oh[3],
                  base + (OFF_BH + bo_ * ASTR + bCol + kofs) * 2);
            ldsm4(ol[0], ol[1], ol[2], ol[3],
                  base + (OFF_BL + bo_ * ASTR + bCol + kofs) * 2);
            #pragma unroll
            for (int mt = 0; mt < 2; mt++) {
                float* c0 = acc[mt * 8 + np * 4 + 0];
                float* c1 = acc[mt * 8 + np * 4 + 1];
                float* c2 = acc[mt * 8 + np * 4 + 2];
                float* c3 = acc[mt * 8 + np * 4 + 3];
                mma16816(c0, ah[mt], eh[0], eh[1]);
                mma16816(c1, ah[mt], eh[2], eh[3]);
                mma16816(c2, ah[mt], oh[0], oh[1]);
                mma16816(c3, ah[mt], oh[2], oh[3]);
                mma16816(c0, al[mt], eh[0], eh[1]);
                mma16816(c1, al[mt], eh[2], eh[3]);
                mma16816(c2, al[mt], oh[0], oh[1]);
                mma16816(c3, al[mt], oh[2], oh[3]);
                mma16816(c0, ah[mt], el[0], el[1]);
                mma16816(c1, ah[mt], el[2], el[3]);
                mma16816(c2, ah[mt], ol[0], ol[1]);
                mma16816(c3, ah[mt], ol[2], ol[3]);
            }
        }
    }
}

// 2-term compute (screen): (Ah+Al)*Bh.
__device__ __forceinline__ void compute_phase2(
    uint32_t base, float (*acc)[4],
    uint32_t aRowB, uint32_t aCol, uint32_t bRow0, uint32_t bCol)
{
    #pragma unroll
    for (int ks = 0; ks < 2; ks++) {
        const uint32_t kofs = ks * 16;
        uint32_t ah[2][4], al[2][4];
        #pragma unroll
        for (int mt = 0; mt < 2; mt++) {
            ldsm4(ah[mt][0], ah[mt][1], ah[mt][2], ah[mt][3],
                  base + (OFF_AH + (aRowB + mt * 16) * ASTR + aCol + kofs) * 2);
            ldsm4(al[mt][0], al[mt][1], al[mt][2], al[mt][3],
                  base + (OFF_AL + (aRowB + mt * 16) * ASTR + aCol + kofs) * 2);
        }
        #pragma unroll
        for (int np = 0; np < 2; np++) {
            const uint32_t be_ = bRow0 + np * 32;
            const uint32_t bo_ = be_ + 16;
            uint32_t eh[4], oh[4];
            ldsm4(eh[0], eh[1], eh[2], eh[3],
                  base + (OFF_BH + be_ * ASTR + bCol + kofs) * 2);
            ldsm4(oh[0], oh[1], oh[2], oh[3],
                  base + (OFF_BH + bo_ * ASTR + bCol + kofs) * 2);
            #pragma unroll
            for (int mt = 0; mt < 2; mt++) {
                float* c0 = acc[mt * 8 + np * 4 + 0];
                float* c1 = acc[mt * 8 + np * 4 + 1];
                float* c2 = acc[mt * 8 + np * 4 + 2];
                float* c3 = acc[mt * 8 + np * 4 + 3];
                mma16816(c0, ah[mt], eh[0], eh[1]);
                mma16816(c1, ah[mt], eh[2], eh[3]);
                mma16816(c2, ah[mt], oh[0], oh[1]);
                mma16816(c3, ah[mt], oh[2], oh[3]);
                mma16816(c0, al[mt], eh[0], eh[1]);
                mma16816(c1, al[mt], eh[2], eh[3]);
                mma16816(c2, al[mt], oh[0], oh[1]);
                mma16816(c3, al[mt], oh[2], oh[3]);
            }
        }
    }
}

// ------------------------- pipelined split-HMMA GEMM (3-term) ---------------
__global__ void __launch_bounds__(256, 2)
k_hgemm(const float* __restrict__ A, int lda, int M, int nkb,
        int bsel, int zfuse, const float* __restrict__ bias,
        float* __restrict__ Cp, int csel0, int ldc, int do_relu)
{
    extern __shared__ __align__(16) __half smh[];
    __shared__ float s_bias[256];

    const int z = zfuse ? blockIdx.z : 0;
    const int csel = csel0 + z;
    const int koff = z * 256;
    float* C = (csel == 1) ? g_A : (csel == 2) ? g_B : Cp;
    const __half* BTh = bsel ? g_W0h : g_Weh;
    const __half* BTl = bsel ? g_W0l : g_Wel;
    const float* bias_eff = (csel == 2) ? nullptr : bias;

    const int tid = threadIdx.x, wid = tid >> 5, lane = tid & 31;
    const int wm = wid & 1, wn = wid >> 1;
    const int row0 = blockIdx.x * 64;
    const int n0 = blockIdx.y * 256;

    s_bias[tid] = bias_eff ? bias_eff[n0 + tid] : 0.f;

    const int ar = tid >> 2, kq = (tid & 3) * 8;
    const int grow = row0 + ar;
    const float4* pA = (const float4*)(A + (size_t)(grow < M ? grow : 0) * lda);

    const uint32_t sb = smem_u32(smh);
    const uint32_t aRowB = wm * 32 + (lane & 15);
    const uint32_t aCol = (lane < 16) ? 0 : 8;
    const uint32_t bRow0 = wn * 64 + (lane & 7) + ((lane >= 16) ? 8 : 0);
    const uint32_t bCol = (lane & 8) ? 8 : 0;

    float acc[16][4];
    #pragma unroll
    for (int i = 0; i < 16; i++)
        #pragma unroll
        for (int j = 0; j < 4; j++) acc[i][j] = 0.f;

    auto ldgA = [&](int kb, float4& r0, float4& r1) {
        int f4 = kb * 8 + (tid & 3) * 2;
        if (grow < M) { r0 = pA[f4]; r1 = pA[f4 + 1]; }
        else { r0 = make_float4(0.f,0.f,0.f,0.f); r1 = r0; }
    };
    auto stsA = [&](int buf, float4 a0, float4 a1) {
        float v[8] = {a0.x, a0.y, a0.z, a0.w, a1.x, a1.y, a1.z, a1.w};
        __half* dh = smh + buf * BUF_HALF + OFF_AH + ar * ASTR + kq;
        __half* dl = smh + buf * BUF_HALF + OFF_AL + ar * ASTR + kq;
        #pragma unroll
        for (int e = 0; e < 8; e++) {
            __half hh = __float2half_rn(v[e]);
            dh[e] = hh;
            dl[e] = __float2half_rn(v[e] - __half2float(hh));
        }
    };
    auto stageB = [&](int kb, int buf) {
        const __half* srcH = BTh + (size_t)(n0 + tid) * 512 + koff + kb * 32;
        const __half* srcL = BTl + (size_t)(n0 + tid) * 512 + koff + kb * 32;
        uint32_t dH = sb + (buf * BUF_HALF + OFF_BH + tid * ASTR) * 2;
        uint32_t dL = sb + (buf * BUF_HALF + OFF_BL + tid * ASTR) * 2;
        #pragma unroll
        for (int q = 0; q < 4; q++) {
            cp16(dH + q * 16, srcH + q * 8);
            cp16(dL + q * 16, srcL + q * 8);
        }
    };

    float4 ra0, ra1;
    ldgA(0, ra0, ra1);
    stsA(0, ra0, ra1);
    stageB(0, 0); CP_COMMIT();
    if (nkb > 1) ldgA(1, ra0, ra1);
    CP_WAIT0();
    __syncthreads();

    for (int kb = 0; kb < nkb; kb++) {
        const int cur = kb & 1;
        if (kb + 1 < nkb) {
            stsA(cur ^ 1, ra0, ra1);
            stageB(kb + 1, cur ^ 1); CP_COMMIT();
            if (kb + 2 < nkb) ldgA(kb + 2, ra0, ra1);
        }
        compute_phase3(sb + cur * BUF_HALF * 2, acc, aRowB, aCol, bRow0, bCol);
        if (kb + 1 < nkb) CP_WAIT0();
        __syncthreads();
    }

    const int g = lane >> 2, tg = lane & 3;
    #pragma unroll
    for (int mt = 0; mt < 2; mt++) {
        const int r0 = row0 + wm * 32 + mt * 16 + g;
        const int r1 = r0 + 8;
        #pragma unroll
        for (int ntc = 0; ntc < 8; ntc++) {
            int c = wn * 64 + ntc * 8 + tg * 2;
            float* a = acc[mt * 8 + ntc];
            float b0v = s_bias[c], b1v = s_bias[c + 1];
            float v00 = a[0] + b0v, v01 = a[1] + b1v;
            float v10 = a[2] + b0v, v11 = a[3] + b1v;
            if (do_relu) {
                v00 = fmaxf(v00, 0.f); v01 = fmaxf(v01, 0.f);
                v10 = fmaxf(v10, 0.f); v11 = fmaxf(v11, 0.f);
            }
            if (r0 < M) *(float2*)&C[(size_t)r0 * ldc + n0 + c] = make_float2(v00, v01);
            if (r1 < M) *(float2*)&C[(size_t)r1 * ldc + n0 + c] = make_float2(v10, v11);
        }
    }
}

// ------------------------- pipelined 2-term HMMA screening ------------------
// (R14 structure + isolated R15 win: .ca weight staging, __ldcg A gathers)
__global__ void __launch_bounds__(256, 2)
k_screen(const float* __restrict__ b1, const float* __restrict__ Wlk,
         const float* __restrict__ blk,
         const int* __restrict__ esrc, const int* __restrict__ edst)
{
    extern __shared__ __align__(16) __half smh[];
    __shared__ float s_n2[64];
    __shared__ float s_lk[4][64];
    __shared__ int s_src[64], s_dst[64];
    __shared__ float s_b1[256], s_wlk[256];

    const int tid = threadIdx.x, wid = tid >> 5, lane = tid & 31;
    const int wm = wid & 1, wn = wid >> 1;
    const int t0 = blockIdx.x * 64;

    if (tid < 64) {
        int t = t0 + tid;
        int s = -1, d = -1;
        if (t < TT) {
            if (t < NE) { s = esrc[t]; d = edst[t]; }
            else        { s = t - NE; }
        }
        s_src[tid] = s; s_dst[tid] = d;
        s_n2[tid] = 0.f;
    }
    s_b1[tid]  = b1[tid];
    s_wlk[tid] = Wlk[tid];
    __syncthreads();

    const int ar = tid >> 2, kq = (tid & 3) * 8;
    const int ss = s_src[ar], dd = s_dst[ar];
    const float4* pA = (const float4*)(g_A + (size_t)(ss < 0 ? 0 : ss) * H0D);
    const float4* pB = (const float4*)(g_B + (size_t)(dd < 0 ? 0 : dd) * H0D);

    const uint32_t sb = smem_u32(smh);
    const uint32_t aRowB = wm * 32 + (lane & 15);
    const uint32_t aCol = (lane < 16) ? 0 : 8;
    const uint32_t bRow0 = wn * 64 + (lane & 7) + ((lane >= 16) ? 8 : 0);
    const uint32_t bCol = (lane & 8) ? 8 : 0;

    float acc[16][4];
    #pragma unroll
    for (int i = 0; i < 16; i++)
        #pragma unroll
        for (int j = 0; j < 4; j++) acc[i][j] = 0.f;

    float n2acc = 0.f;

    auto ldgA = [&](int kb, float4* r) {
        int f4 = kb * 8 + (tid & 3) * 2;
        if (ss >= 0) {
            r[0] = __ldcg(pA + f4); r[1] = __ldcg(pA + f4 + 1);
            if (dd >= 0) { r[2] = __ldcg(pB + f4); r[3] = __ldcg(pB + f4 + 1); }
            else { r[2] = make_float4(0.f,0.f,0.f,0.f); r[3] = r[2]; }
        } else {
            r[0] = make_float4(0.f,0.f,0.f,0.f);
            r[1] = r[0]; r[2] = r[0]; r[3] = r[0];
        }
    };
    auto stsA = [&](int buf, const float4* r) {
        float v[8] = {r[0].x + r[2].x, r[0].y + r[2].y,
                      r[0].z + r[2].z, r[0].w + r[2].w,
                      r[1].x + r[3].x, r[1].y + r[3].y,
                      r[1].z + r[3].z, r[1].w + r[3].w};
        __half* dh = smh + buf * SBUF_HALF + OFF_AH + ar * ASTR + kq;
        __half* dl = smh + buf * SBUF_HALF + OFF_AL + ar * ASTR + kq;
        #pragma unroll
        for (int e = 0; e < 8; e++) {
            float x = fmaxf(v[e], 0.f);
            __half hh = __float2half_rn(x);
            dh[e] = hh;
            dl[e] = __float2half_rn(x - __half2float(hh));
            n2acc = fmaf(x, x, n2acc);
        }
    };
    auto stageB = [&](int kb, int buf) {
        const __half* srcH = g_W1h + (size_t)tid * H0D + kb * 32;
        uint32_t dH = sb + (buf * SBUF_HALF + OFF_BH + tid * ASTR) * 2;
        #pragma unroll
        for (int q = 0; q < 4; q++)
            cp16ca(dH + q * 16, srcH + q * 8);
    };

    float4 ra[4];
    ldgA(0, ra);
    stsA(0, ra);
    stageB(0, 0); CP_COMMIT();
    ldgA(1, ra);
    CP_WAIT0();
    __syncthreads();

    const int nkb = 16;
    for (int kb = 0; kb < nkb; kb++) {
        const int cur = kb & 1;
        if (kb + 1 < nkb) {
            stsA(cur ^ 1, ra);
            stageB(kb + 1, cur ^ 1); CP_COMMIT();
            if (kb + 2 < nkb) ldgA(kb + 2, ra);
        }
        compute_phase2(sb + cur * SBUF_HALF * 2, acc, aRowB, aCol, bRow0, bCol);
        if (kb + 1 < nkb) CP_WAIT0();
        __syncthreads();
    }

    if (ss >= 0) atomicAdd(&s_n2[ar], n2acc);

    const int g = lane >> 2, tg = lane & 3;
    float sum[2][2] = {{0.f, 0.f}, {0.f, 0.f}};
    #pragma unroll
    for (int mt = 0; mt < 2; mt++) {
        #pragma unroll
        for (int ntc = 0; ntc < 8; ntc++) {
            int c = wn * 64 + ntc * 8 + tg * 2;
            float* a = acc[mt * 8 + ntc];
            float b10 = s_b1[c],     w0 = s_wlk[c];
            float b11 = s_b1[c + 1], w1 = s_wlk[c + 1];
            sum[mt][0] += fmaxf(a[0] + b10, 0.f) * w0 +
                          fmaxf(a[1] + b11, 0.f) * w1;
            sum[mt][1] += fmaxf(a[2] + b10, 0.f) * w0 +
                          fmaxf(a[3] + b11, 0.f) * w1;
        }
    }
    #pragma unroll
    for (int mt = 0; mt < 2; mt++) {
        sum[mt][0] += __shfl_xor_sync(0xffffffffu, sum[mt][0], 1);
        sum[mt][0] += __shfl_xor_sync(0xffffffffu, sum[mt][0], 2);
        sum[mt][1] += __shfl_xor_sync(0xffffffffu, sum[mt][1], 1);
        sum[mt][1] += __shfl_xor_sync(0xffffffffu, sum[mt][1], 2);
    }
    __syncthreads();
    if (tg == 0) {
        #pragma unroll
        for (int mt = 0; mt < 2; mt++) {
            s_lk[wn][wm * 32 + mt * 16 + g]     = sum[mt][0];
            s_lk[wn][wm * 32 + mt * 16 + g + 8] = sum[mt][1];
        }
    }
    __syncthreads();

    if (tid < 64) {
        int t = t0 + tid;
        if (t < TT) {
            float lk = s_lk[0][tid] + s_lk[1][tid] + s_lk[2][tid] +
                       s_lk[3][tid] + blk[0];
            float err = (1.02f * g_C2 + KACC * g_C) * sqrtf(s_n2[tid]) + TINY;
            g_lk[t] = lk;
            g_elk[t] = err;
            atomicMax(&g_segscr[s_src[tid]], fenc(lk - err));
        }
    }
}

// ------------------------- candidate compaction -----------------------------
__global__ void k_compact(const int* __restrict__ esrc) {
    int t = blockIdx.x * blockDim.x + threadIdx.x;
    if (t >= TT) return;
    int s = (t < NE) ? esrc[t] : (t - NE);
    if (fenc(g_lk[t] + g_elk[t]) >= g_segscr[s]) {
        int slot = atomicAdd(&g_ncand, 1);
        g_cand[slot] = t;
        g_slot[t] = slot;
    }
}

// ------------------------- exact fp32 rescore of candidates (R14) -----------
__global__ __launch_bounds__(256) void k_rescore(
    const float* __restrict__ W1, const float* __restrict__ b1,
    const float* __restrict__ Wlk, const float* __restrict__ blk,
    const int* __restrict__ esrc, const int* __restrict__ edst)
{
    const int c0 = blockIdx.x * 64;
    const int nc = g_ncand;
    if (c0 >= nc) return;

    __shared__ float Zs[32][68];
    __shared__ float Bs[32 * 256];
    __shared__ int s_src[64], s_dst[64], s_t[64];

    const int tid = threadIdx.x;
    const int cg = tid & 31, eg = tid >> 5;

    if (tid < 64) {
        int c = c0 + tid;
        int s = -1, d = -1, t = -1;
        if (c < nc) {
            t = g_cand[c];
            if (t < NE) { s = esrc[t]; d = edst[t]; }
            else        { s = t - NE; }
        }
        s_src[tid] = s; s_dst[tid] = d; s_t[tid] = t;
    }
    __syncthreads();

    float acc[8][8];
    #pragma unroll
    for (int i = 0; i < 8; i++)
        #pragma unroll
        for (int j = 0; j < 8; j++) acc[i][j] = 0.f;

    for (int k0 = 0; k0 < H0D; k0 += 32) {
        #pragma unroll
        for (int l = 0; l < 8; l++) {
            int idx = tid + l * 256;
            int e = idx >> 5, kk = idx & 31;
            int s = s_src[e];
            float v = 0.f;
            if (s >= 0) {
                v = g_A[(size_t)s * H0D + k0 + kk];
                int d = s_dst[e];
                if (d >= 0) v += g_B[(size_t)d * H0D + k0 + kk];
                v = fmaxf(v, 0.f);
            }
            Zs[kk][e] = v;
        }
        #pragma unroll
        for (int l = 0; l < 8; l++) {
            int idx4 = tid + l * 256;
            int kk = idx4 >> 6, c = (idx4 << 2) & 255;
            *(float4*)&Bs[kk * 256 + c] =
                *(const float4*)&W1[(size_t)(k0 + kk) * H1D + c];
        }
        __syncthreads();
        #pragma unroll
        for (int kk = 0; kk < 32; kk++) {
            float a[8], b[8];
            *(float4*)(a)     = *(const float4*)&Zs[kk][eg * 8];
            *(float4*)(a + 4) = *(const float4*)&Zs[kk][eg * 8 + 4];
            *(float4*)(b)     = *(const float4*)&Bs[kk * 256 + cg * 8];
            *(float4*)(b + 4) = *(const float4*)&Bs[kk * 256 + cg * 8 + 4];
            #pragma unroll
            for (int i = 0; i < 8; i++)
                #pragma unroll
                for (int j = 0; j < 8; j++)
                    acc[i][j] = fmaf(a[i], b[j], acc[i][j]);
        }
        __syncthreads();
    }

    float bb[8], wl[8];
    #pragma unroll
    for (int j = 0; j < 8; j++) {
        bb[j] = b1[cg * 8 + j];
        wl[j] = Wlk[cg * 8 + j];
    }

    float lkp[8];
    #pragma unroll
    for (int i = 0; i < 8; i++) {
        int e = eg * 8 + i;
        int c = c0 + e;
        float h[8];
        float p = 0.f;
        #pragma unroll
        for (int j = 0; j < 8; j++) {
            h[j] = fmaxf(acc[i][j] + bb[j], 0.f);
            p = fmaf(h[j], wl[j], p);
        }
        if (s_t[e] >= 0) {
            *(float4*)&g_h_cand[(size_t)c * H1D + cg * 8]     = *(float4*)h;
            *(float4*)&g_h_cand[(size_t)c * H1D + cg * 8 + 4] = *(float4*)(h + 4);
        }
        #pragma unroll
        for (int off = 16; off; off >>= 1)
            p += __shfl_xor_sync(0xffffffffu, p, off);
        lkp[i] = p;
    }

    if (cg == 0) {
        float lb = blk[0];
        #pragma unroll
        for (int i = 0; i < 8; i++) {
            int e = eg * 8 + i;
            int t = s_t[e];
            if (t >= 0) {
                float lk = lkp[i] + lb;
                unsigned long long key =
                    ((unsigned long long)fenc(lk) << 32) | (unsigned int)t;
                atomicMax(&g_seg2[s_src[e]], key);
            }
        }
    }
}

// ------------------------- winner decode + action head (R14) ----------------
__global__ void k_final(const float* __restrict__ Wa, const float* __restrict__ ba,
                        const int* __restrict__ edst)
{
    int warp = (blockIdx.x * blockDim.x + threadIdx.x) >> 5;
    int lane = threadIdx.x & 31;
    if (warp >= NN) return;
    unsigned long long key = g_seg2[warp];
    int win = (int)(unsigned int)(key & 0xffffffffull);
    int chosen = (win < NE) ? edst[win] : -1;

    const float* h = &g_h_cand[(size_t)g_slot[win] * H1D];
    float s0 = 0.f, s1 = 0.f;
    #pragma unroll
    for (int j = 0; j < 8; j++) {
        float hv = h[lane + j * 32];
        s0 = fmaf(hv, Wa[(lane + j * 32) * 2 + 0], s0);
        s1 = fmaf(hv, Wa[(lane + j * 32) * 2 + 1], s1);
    }
    #pragma unroll
    for (int off = 16; off; off >>= 1) {
        s0 += __shfl_xor_sync(0xffffffffu, s0, off);
        s1 += __shfl_xor_sync(0xffffffffu, s1, off);
    }
    if (lane == 0) {
        float l0 = s0 + ba[0], l1 = s1 + ba[1];
        if (chosen >= 0 && (l1 > l0))
            atomicMax(&g_owner[chosen], warp);
    }
}

// ------------------------- compact update targets ---------------------------
__global__ void k_compact2() {
    int t = blockIdx.x * blockDim.x + threadIdx.x;
    if (t < NN && g_owner[t] >= 0) {
        int s = atomicAdd(&g_nupd, 1);
        g_upd[s] = t;
    }
}

// ------------------------- split-HMMA update of chosen rows (R14) -----------
__global__ void __launch_bounds__(256, 2)
k_updval(const float* __restrict__ feature, const float* __restrict__ be,
         float* __restrict__ out)
{
    const int c0 = blockIdx.x * 64;
    const int nu = g_nupd;
    if (c0 >= nu) return;

    extern __shared__ __align__(16) __half smh[];
    __shared__ int s_t[64], s_i[64];
    __shared__ float s_be[256];

    const int tid = threadIdx.x, wid = tid >> 5, lane = tid & 31;
    const int wm = wid & 1, wn = wid >> 1;

    if (tid < 64) {
        int c = c0 + tid;
        int t = (c < nu) ? g_upd[c] : -1;
        s_t[tid] = t;
        s_i[tid] = (t >= 0) ? g_owner[t] : 0;
    }
    s_be[tid] = be[tid];
    __syncthreads();

    const int ar = tid >> 2, kq = (tid & 3) * 8;
    const int tt = s_t[ar], ii = s_i[ar];
    const float4* pA = (const float4*)(feature + (size_t)(tt < 0 ? 0 : tt) * FIN);
    const float4* pB = (const float4*)(feature + (size_t)ii * FIN);

    const uint32_t sb = smem_u32(smh);
    const uint32_t aRowB = wm * 32 + (lane & 15);
    const uint32_t aCol = (lane < 16) ? 0 : 8;
    const uint32_t bRow0 = wn * 64 + (lane & 7) + ((lane >= 16) ? 8 : 0);
    const uint32_t bCol = (lane & 8) ? 8 : 0;

    float acc[16][4];
    #pragma unroll
    for (int i = 0; i < 16; i++)
        #pragma unroll
        for (int j = 0; j < 4; j++) acc[i][j] = 0.f;

    auto ldgA = [&](int kb, float4* r) {
        int f4 = kb * 8 + (tid & 3) * 2;
        if (tt >= 0) {
            r[0] = pA[f4]; r[1] = pA[f4 + 1];
            r[2] = pB[f4]; r[3] = pB[f4 + 1];
        } else {
            r[0] = make_float4(0.f,0.f,0.f,0.f);
            r[1] = r[0]; r[2] = r[0]; r[3] = r[0];
        }
    };
    auto stsA = [&](int buf, const float4* r) {
        float v[8] = {0.5f * (r[0].x + r[2].x), 0.5f * (r[0].y + r[2].y),
                      0.5f * (r[0].z + r[2].z), 0.5f * (r[0].w + r[2].w),
                      0.5f * (r[1].x + r[3].x), 0.5f * (r[1].y + r[3].y),
                      0.5f * (r[1].z + r[3].z), 0.5f * (r[1].w + r[3].w)};
        __half* dh = smh + buf * BUF_HALF + OFF_AH + ar * ASTR + kq;
        __half* dl = smh + buf * BUF_HALF + OFF_AL + ar * ASTR + kq;
        #pragma unroll
        for (int e = 0; e < 8; e++) {
            __half hh = __float2half_rn(v[e]);
            dh[e] = hh;
            dl[e] = __float2half_rn(v[e] - __half2float(hh));
        }
    };
    auto stageB = [&](int kb, int buf) {
        const __half* srcH = g_Weh + (size_t)tid * FIN + kb * 32;
        const __half* srcL = g_Wel + (size_t)tid * FIN + kb * 32;
        uint32_t dH = sb + (buf * BUF_HALF + OFF_BH + tid * ASTR) * 2;
        uint32_t dL = sb + (buf * BUF_HALF + OFF_BL + tid * ASTR) * 2;
        #pragma unroll
        for (int q = 0; q < 4; q++) {
            cp16(dH + q * 16, srcH + q * 8);
            cp16(dL + q * 16, srcL + q * 8);
        }
    };

    float4 ra[4];
    ldgA(0, ra);
    stsA(0, ra);
    stageB(0, 0); CP_COMMIT();
    ldgA(1, ra);
    CP_WAIT0();
    __syncthreads();

    const int nkb = 16;
    for (int kb = 0; kb < nkb; kb++) {
        const int cur = kb & 1;
        if (kb + 1 < nkb) {
            stsA(cur ^ 1, ra);
            stageB(kb + 1, cur ^ 1); CP_COMMIT();
            if (kb + 2 < nkb) ldgA(kb + 2, ra);
        }
        compute_phase3(sb + cur * BUF_HALF * 2, acc, aRowB, aCol, bRow0, bCol);
        if (kb + 1 < nkb) CP_WAIT0();
        __syncthreads();
    }

    const int g = lane >> 2, tg = lane & 3;
    #pragma unroll
    for (int mt = 0; mt < 2; mt++) {
        const int e0 = wm * 32 + mt * 16 + g;
        const int e1 = e0 + 8;
        const int t0r = s_t[e0], t1r = s_t[e1];
        #pragma unroll
        for (int ntc = 0; ntc < 8; ntc++) {
            int c = wn * 64 + ntc * 8 + tg * 2;
            float* a = acc[mt * 8 + ntc];
            float b0v = s_be[c], b1v = s_be[c + 1];
            float v00 = fmaxf(a[0] + b0v, 0.f), v01 = fmaxf(a[1] + b1v, 0.f);
            float v10 = fmaxf(a[2] + b0v, 0.f), v11 = fmaxf(a[3] + b1v, 0.f);
            if (t0r >= 0) *(float2*)&out[(size_t)t0r * ED + c] = make_float2(v00, v01);
            if (t1r >= 0) *(float2*)&out[(size_t)t1r * ED + c] = make_float2(v10, v11);
        }
    }
}

// ---------------------------------------------------------------------------
extern "C" void kernel_launch(void* const* d_in, const int* in_sizes, int n_in,
                              void* d_out, int out_size) {
    const float* feature = (const float*)d_in[0];
    const float* We      = (const float*)d_in[1];
    const float* be      = (const float*)d_in[2];
    const float* W0      = (const float*)d_in[3];
    const float* b0      = (const float*)d_in[4];
    const float* W1      = (const float*)d_in[5];
    const float* b1      = (const float*)d_in[6];
    const float* Wlk     = (const float*)d_in[7];
    const float* blk     = (const float*)d_in[8];
    const float* Wa      = (const float*)d_in[9];
    const float* ba      = (const float*)d_in[10];
    const int*   esrc    = (const int*)d_in[11];
    const int*   edst    = (const int*)d_in[12];
    float* out = (float*)d_out;

    static int smem_set = 0;
    if (!smem_set) {
        cudaFuncSetAttribute(k_screen,
                             cudaFuncAttributeMaxDynamicSharedMemorySize,
                             SCREEN_SMEM);
        cudaFuncSetAttribute(k_hgemm,
                             cudaFuncAttributeMaxDynamicSharedMemorySize,
                             HMMA_SMEM);
        cudaFuncSetAttribute(k_updval,
                             cudaFuncAttributeMaxDynamicSharedMemorySize,
                             HMMA_SMEM);
        smem_set = 1;
    }

    k_prep<<<1 + (H0D * H0D + 255) / 256, 256>>>(W1, We, W0, Wlk);
    k_hgemm<<<dim3(157, 1, 1), 256, HMMA_SMEM>>>(
        feature, FIN, NN, 16, 0, 0, be, out, 0, ED, 1);
    k_hgemm<<<dim3(157, 2, 2), 256, HMMA_SMEM>>>(
        out, ED, NN, 8, 1, 1, b0, nullptr, 1, H0D, 0);
    // launch #4 (profiled): 2-term screening
    k_screen<<<(TT + 63) / 64, 256, SCREEN_SMEM>>>(b1, Wlk, blk, esrc, edst);

    k_compact<<<(TT + 255) / 256, 256>>>(esrc);
    k_rescore<<<(TT + 63) / 64, 256>>>(W1, b1, Wlk, blk, esrc, edst);
    k_final<<<(NN * 32 + 255) / 256, 256>>>(Wa, ba, edst);
    k_compact2<<<(NN + 255) / 256, 256>>>();
    k_updval<<<(NN + 63) / 64, 256, HMMA_SMEM>>>(feature, be, out);
}